// round 15
// baseline (speedup 1.0000x reference)
#include <cuda_runtime.h>

#define NN 50000
#define EE 400000

// ---------------- device scratch (no allocations allowed) ----------------
// relation order: 0=tt, 1=aa, 2=at, 3=ta   (matches e_tt,e_aa,e_at,e_ta inputs)
// dst type:       tt->tx, aa->ad, at->tx, ta->ad
__device__ float g_s[4][NN * 128];     // layer0 neighbor sums (raw x dim)
__device__ float g_h[2][NN * 256];     // layer0 hidden (0=tx, 1=ad)
__device__ float g_WB[2][384 * 256];   // combined layer0 weights, [k][n] layout
__device__ float g_bias[2][256];       // combined layer0 bias
__device__ int   g_cnt[4][NN];         // in-degree per relation
__device__ float g_inv[4][NN];         // 1/max(cnt,1)
__device__ float g_z[4][NN * 2];       // layer1 pre-transformed messages (dim 2!)
__device__ float g_sum[4][NN * 2];     // layer1 scatter sums

// ---------------- packed f32x2 helpers (sm_103a FFMA2) ----------------
__device__ __forceinline__ unsigned long long pk2(float a, float b) {
    unsigned long long r;
    asm("mov.b64 %0, {%1,%2};" : "=l"(r) : "f"(a), "f"(b));
    return r;
}
__device__ __forceinline__ void fma2(unsigned long long& d, unsigned long long a, unsigned long long b) {
    asm("fma.rn.f32x2 %0, %1, %2, %0;" : "+l"(d) : "l"(a), "l"(b));
}
__device__ __forceinline__ float2 up2(unsigned long long v) {
    float x, y;
    asm("mov.b64 {%0,%1}, %2;" : "=f"(x), "=f"(y) : "l"(v));
    return make_float2(x, y);
}

// ---------------- zero kernels ----------------
__global__ void k_zeroS() {
    size_t i = (size_t)blockIdx.x * blockDim.x + threadIdx.x;
    float4* p = (float4*)&g_s[0][0];
    if (i < (size_t)4 * NN * 128 / 4) p[i] = make_float4(0.f, 0.f, 0.f, 0.f);
}
__global__ void k_zeroMisc() {
    int i = blockIdx.x * blockDim.x + threadIdx.x;
    if (i < 4 * NN) ((int*)g_cnt)[i] = 0;
    if (i < 4 * NN * 2) ((float*)g_sum)[i] = 0.f;
}

// ---------------- build combined layer0 weights ----------------
// WB[type][k][n]: k<128 -> Wl_a[n][k]; k<256 -> Wl_b[n][k-128]; else Wr_a[n][k-256]+Wr_b[n][k-256]
__global__ void k_prep(const float* __restrict__ Wl_a, const float* __restrict__ Wl_b,
                       const float* __restrict__ Wr_a, const float* __restrict__ Wr_b,
                       const float* __restrict__ bl_a, const float* __restrict__ bl_b,
                       int type) {
    int idx = blockIdx.x * blockDim.x + threadIdx.x;
    if (idx < 384 * 256) {
        int k = idx >> 8, n = idx & 255;
        float v;
        if (k < 128)       v = __ldg(Wl_a + n * 128 + k);
        else if (k < 256)  v = __ldg(Wl_b + n * 128 + (k - 128));
        else               v = __ldg(Wr_a + n * 128 + (k - 256)) + __ldg(Wr_b + n * 128 + (k - 256));
        g_WB[type][idx] = v;
    }
    if (idx < 256) g_bias[type][idx] = __ldg(bl_a + idx) + __ldg(bl_b + idx);
}

// ---------------- layer0 scatter: one warp per edge, red.v4 ----------------
__global__ __launch_bounds__(256) void k_scatter0(const float* __restrict__ x,
                                                  const int* __restrict__ e, int rel) {
    int gt = blockIdx.x * blockDim.x + threadIdx.x;
    int w = gt >> 5, lane = gt & 31;
    if (w >= EE) return;
    int src = __ldg(e + w);
    int dst = __ldg(e + EE + w);
    float4 v = __ldg((const float4*)(x + (size_t)src * 128 + lane * 4));
    float* sp = g_s[rel] + (size_t)dst * 128 + lane * 4;
    asm volatile("red.global.add.v4.f32 [%0], {%1,%2,%3,%4};"
                 :: "l"(sp), "f"(v.x), "f"(v.y), "f"(v.z), "f"(v.w) : "memory");
    if (lane == 0) atomicAdd(&g_cnt[rel][dst], 1);
}

__global__ void k_inv() {
    int i = blockIdx.x * blockDim.x + threadIdx.x;
    if (i >= 4 * NN) return;
    int r = i / NN, n = i - r * NN;
    g_inv[r][n] = 1.0f / fmaxf((float)g_cnt[r][n], 1.0f);
}

// ---------------- layer0 fused GEMM: [50000,384] x [384,256], relu epilogue ----------------
// A = [ s_A*invA | s_B*invB | x ] virtual concat. BM=128 BN=64 BK=32, 256 thr, 8x4 micro, FFMA2.
__global__ __launch_bounds__(256, 2) void k_gemm0(const float* __restrict__ x, int type) {
    __shared__ float As[32][132];
    __shared__ float Bs[32][64];
    __shared__ float sc0[128];
    __shared__ float sc1[128];

    const float* sA   = g_s[type];
    const float* sB   = g_s[2 + type];
    const float* WB   = g_WB[type];
    const float* bias = g_bias[type];
    float*       h    = g_h[type];

    int tid = threadIdx.x;
    int rb = blockIdx.x * 128;
    int nb = blockIdx.y * 64;

    if (tid < 128) {
        int r = rb + tid;
        sc0[tid] = (r < NN) ? g_inv[type][r] : 0.f;
        sc1[tid] = (r < NN) ? g_inv[2 + type][r] : 0.f;
    }
    __syncthreads();

    const int rA    = tid >> 1;           // 0..127 row within A tile
    const int kq    = (tid & 1) * 16;     // 0 or 16 (k offset in tile)
    const int rBk   = tid >> 3;           // 0..31 k row for B tile
    const int nq    = (tid & 7) * 8;      // col offset for B tile
    const int mbase = (tid >> 4) * 8;     // 8-row micro tile base
    const int nbase = (tid & 15) * 4;     // 4-col micro tile base

    const bool okA = (rb + rA) < NN;
    const size_t arow = (size_t)(okA ? (rb + rA) : 0) * 128;

    unsigned long long acc[4][4];
#pragma unroll
    for (int i = 0; i < 4; i++)
#pragma unroll
        for (int j = 0; j < 4; j++) acc[i][j] = 0ull;

#pragma unroll 1
    for (int it12 = 0; it12 < 12; ++it12) {
        int seg = it12 >> 2;            // 0: s_A, 1: s_B, 2: x
        int it  = it12 & 3;
        const float* sp = (seg == 0) ? sA : ((seg == 1) ? sB : x);
        float scale = (seg == 0) ? sc0[rA] : ((seg == 1) ? sc1[rA] : 1.f);

        const float* ap = sp + arow + it * 32 + kq;
#pragma unroll
        for (int u = 0; u < 4; ++u) {
            float4 v = okA ? __ldg((const float4*)(ap + 4 * u)) : make_float4(0.f, 0.f, 0.f, 0.f);
            int kk = kq + 4 * u;
            As[kk + 0][rA] = v.x * scale;
            As[kk + 1][rA] = v.y * scale;
            As[kk + 2][rA] = v.z * scale;
            As[kk + 3][rA] = v.w * scale;
        }
        const float* bp = WB + (size_t)(seg * 128 + it * 32 + rBk) * 256 + nb + nq;
        *(float4*)&Bs[rBk][nq]     = __ldg((const float4*)bp);
        *(float4*)&Bs[rBk][nq + 4] = __ldg((const float4*)(bp + 4));
        __syncthreads();

#pragma unroll
        for (int kk = 0; kk < 32; ++kk) {
            const ulonglong2 a01 = *(const ulonglong2*)&As[kk][mbase];
            const ulonglong2 a23 = *(const ulonglong2*)&As[kk][mbase + 4];
            const float4 bv = *(const float4*)&Bs[kk][nbase];
            unsigned long long b0 = pk2(bv.x, bv.x);
            unsigned long long b1 = pk2(bv.y, bv.y);
            unsigned long long b2 = pk2(bv.z, bv.z);
            unsigned long long b3 = pk2(bv.w, bv.w);
            fma2(acc[0][0], a01.x, b0); fma2(acc[0][1], a01.x, b1); fma2(acc[0][2], a01.x, b2); fma2(acc[0][3], a01.x, b3);
            fma2(acc[1][0], a01.y, b0); fma2(acc[1][1], a01.y, b1); fma2(acc[1][2], a01.y, b2); fma2(acc[1][3], a01.y, b3);
            fma2(acc[2][0], a23.x, b0); fma2(acc[2][1], a23.x, b1); fma2(acc[2][2], a23.x, b2); fma2(acc[2][3], a23.x, b3);
            fma2(acc[3][0], a23.y, b0); fma2(acc[3][1], a23.y, b1); fma2(acc[3][2], a23.y, b2); fma2(acc[3][3], a23.y, b3);
        }
        __syncthreads();
    }

    float4 bv = __ldg((const float4*)&bias[nb + nbase]);
#pragma unroll
    for (int p = 0; p < 4; ++p) {
        float2 c0 = up2(acc[p][0]);
        float2 c1 = up2(acc[p][1]);
        float2 c2 = up2(acc[p][2]);
        float2 c3 = up2(acc[p][3]);
        int r0 = rb + mbase + 2 * p;
        if (r0 < NN) {
            float4 o;
            o.x = fmaxf(c0.x + bv.x, 0.f);
            o.y = fmaxf(c1.x + bv.y, 0.f);
            o.z = fmaxf(c2.x + bv.z, 0.f);
            o.w = fmaxf(c3.x + bv.w, 0.f);
            *(float4*)&h[(size_t)r0 * 256 + nb + nbase] = o;
        }
        if (r0 + 1 < NN) {
            float4 o;
            o.x = fmaxf(c0.y + bv.x, 0.f);
            o.y = fmaxf(c1.y + bv.y, 0.f);
            o.z = fmaxf(c2.y + bv.z, 0.f);
            o.w = fmaxf(c3.y + bv.w, 0.f);
            *(float4*)&h[(size_t)(r0 + 1) * 256 + nb + nbase] = o;
        }
    }
}

// ---------------- layer1 node transform: z (dim 2 per relation) + self term into out ----------------
// warp per node; type0 (tx): zA=g_z[0] (Wl1_tt), zB=g_z[3] (Wl1_ta); type1 (ad): zA=g_z[1], zB=g_z[2]
__global__ __launch_bounds__(256) void k_l1(const float* __restrict__ WlA, const float* __restrict__ WlB,
                                            const float* __restrict__ WrA, const float* __restrict__ WrB,
                                            const float* __restrict__ blA, const float* __restrict__ blB,
                                            int type, float* __restrict__ out) {
    int gt = blockIdx.x * blockDim.x + threadIdx.x;
    int w = gt >> 5, lane = gt & 31;
    if (w >= NN) return;
    const float* hp = g_h[type] + (size_t)w * 256 + lane * 8;
    float4 h0 = __ldg((const float4*)hp);
    float4 h1 = __ldg((const float4*)(hp + 4));
    float hv[8] = {h0.x, h0.y, h0.z, h0.w, h1.x, h1.y, h1.z, h1.w};
    float a0 = 0, a1 = 0, a2 = 0, a3 = 0, a4 = 0, a5 = 0;
    int off = lane * 8;
#pragma unroll
    for (int u = 0; u < 8; ++u) {
        int k = off + u;
        float v = hv[u];
        a0 += v * __ldg(WlA + k);       a1 += v * __ldg(WlA + 256 + k);
        a2 += v * __ldg(WlB + k);       a3 += v * __ldg(WlB + 256 + k);
        a4 += v * (__ldg(WrA + k)       + __ldg(WrB + k));
        a5 += v * (__ldg(WrA + 256 + k) + __ldg(WrB + 256 + k));
    }
#pragma unroll
    for (int o = 16; o > 0; o >>= 1) {
        a0 += __shfl_xor_sync(0xffffffffu, a0, o);
        a1 += __shfl_xor_sync(0xffffffffu, a1, o);
        a2 += __shfl_xor_sync(0xffffffffu, a2, o);
        a3 += __shfl_xor_sync(0xffffffffu, a3, o);
        a4 += __shfl_xor_sync(0xffffffffu, a4, o);
        a5 += __shfl_xor_sync(0xffffffffu, a5, o);
    }
    if (lane == 0) {
        float* zA = g_z[type];
        float* zB = g_z[3 - type];
        zA[(size_t)w * 2]     = a0;
        zA[(size_t)w * 2 + 1] = a1;
        zB[(size_t)w * 2]     = a2;
        zB[(size_t)w * 2 + 1] = a3;
        out[(size_t)w * 2]     = a4 + __ldg(blA)     + __ldg(blB);
        out[(size_t)w * 2 + 1] = a5 + __ldg(blA + 1) + __ldg(blB + 1);
    }
}

// ---------------- layer1 scatter: thread per edge, dim 2 only ----------------
__global__ __launch_bounds__(256) void k_scatter1(const int* __restrict__ e, int rel) {
    int j = blockIdx.x * blockDim.x + threadIdx.x;
    if (j >= EE) return;
    int src = __ldg(e + j);
    int dst = __ldg(e + EE + j);
    const float* zp = g_z[rel] + (size_t)src * 2;
    float zx = __ldg(zp), zy = __ldg(zp + 1);
    float* sp = g_sum[rel] + (size_t)dst * 2;
    asm volatile("red.global.add.v2.f32 [%0], {%1,%2};"
                 :: "l"(sp), "f"(zx), "f"(zy) : "memory");
}

// ---------------- final combine: out += mean-agg of z ----------------
__global__ void k_combine(float* __restrict__ out) {
    int i = blockIdx.x * blockDim.x + threadIdx.x;
    if (i >= NN) return;
    float itt = g_inv[0][i], iaa = g_inv[1][i], iat = g_inv[2][i], ita = g_inv[3][i];
    size_t i2 = (size_t)i * 2;
    out[i2]     += g_sum[0][i2] * itt     + g_sum[2][i2] * iat;
    out[i2 + 1] += g_sum[0][i2 + 1] * itt + g_sum[2][i2 + 1] * iat;
    out[(size_t)NN * 2 + i2]     += g_sum[1][i2] * iaa     + g_sum[3][i2] * ita;
    out[(size_t)NN * 2 + i2 + 1] += g_sum[1][i2 + 1] * iaa + g_sum[3][i2 + 1] * ita;
}

extern "C" void kernel_launch(void* const* d_in, const int* in_sizes, int n_in,
                              void* d_out, int out_size) {
    const float* x_tx = (const float*)d_in[0];
    const float* x_ad = (const float*)d_in[1];
    const int* e_tt = (const int*)d_in[2];
    const int* e_aa = (const int*)d_in[3];
    const int* e_at = (const int*)d_in[4];
    const int* e_ta = (const int*)d_in[5];
    float* out = (float*)d_out;

    // zero scratch
    k_zeroS<<<25000, 256>>>();
    k_zeroMisc<<<1563, 256>>>();

    // combined layer0 weights: type0 (tx dst): Wl0_tt, Wl0_at, Wr0_tt+Wr0_at
    k_prep<<<384, 256>>>((const float*)d_in[6],  (const float*)d_in[12],
                         (const float*)d_in[8],  (const float*)d_in[14],
                         (const float*)d_in[7],  (const float*)d_in[13], 0);
    // type1 (ad dst): Wl0_aa, Wl0_ta, Wr0_aa+Wr0_ta
    k_prep<<<384, 256>>>((const float*)d_in[9],  (const float*)d_in[15],
                         (const float*)d_in[11], (const float*)d_in[17],
                         (const float*)d_in[10], (const float*)d_in[16], 1);

    // layer0 edge aggregation (src features per relation)
    k_scatter0<<<50000, 256>>>(x_tx, e_tt, 0);
    k_scatter0<<<50000, 256>>>(x_ad, e_aa, 1);
    k_scatter0<<<50000, 256>>>(x_ad, e_at, 2);
    k_scatter0<<<50000, 256>>>(x_tx, e_ta, 3);
    k_inv<<<782, 256>>>();

    // layer0 fused GEMM + relu
    k_gemm0<<<dim3(391, 4), 256>>>(x_tx, 0);
    k_gemm0<<<dim3(391, 4), 256>>>(x_ad, 1);

    // layer1: transform-first (dim 2), self term written straight to out
    // tx: WlA=Wl1_tt[18], WlB=Wl1_ta[27], Wr1_tt[20]+Wr1_at[26], bl1_tt[19]+bl1_at[25]
    k_l1<<<6250, 256>>>((const float*)d_in[18], (const float*)d_in[27],
                        (const float*)d_in[20], (const float*)d_in[26],
                        (const float*)d_in[19], (const float*)d_in[25], 0, out);
    // ad: WlA=Wl1_aa[21], WlB=Wl1_at[24], Wr1_aa[23]+Wr1_ta[29], bl1_aa[22]+bl1_ta[28]
    k_l1<<<6250, 256>>>((const float*)d_in[21], (const float*)d_in[24],
                        (const float*)d_in[23], (const float*)d_in[29],
                        (const float*)d_in[22], (const float*)d_in[28], 1, out + (size_t)NN * 2);

    // layer1 edge aggregation at dim 2
    k_scatter1<<<1563, 256>>>(e_tt, 0);
    k_scatter1<<<1563, 256>>>(e_aa, 1);
    k_scatter1<<<1563, 256>>>(e_at, 2);
    k_scatter1<<<1563, 256>>>(e_ta, 3);

    k_combine<<<196, 256>>>(out);
}

// round 16
// speedup vs baseline: 1.1982x; 1.1982x over previous
#include <cuda_runtime.h>
#include <cuda_bf16.h>
#include <cstdint>

#define NN 50000
#define EE 400000

// ---------------- device scratch ----------------
// relation order: 0=tt, 1=aa, 2=at, 3=ta; dst type: tt->tx, aa->ad, at->tx, ta->ad
__device__ float g_s[4][NN * 128];            // layer0 neighbor sums
__device__ float g_h[2][NN * 256];            // layer0 hidden
__device__ __nv_bfloat16 g_WBh[2][256 * 384]; // combined layer0 weights hi, [n][k]
__device__ __nv_bfloat16 g_WBl[2][256 * 384]; // combined layer0 weights lo, [n][k]
__device__ float g_bias[2][256];
__device__ int   g_cnt[4][NN];
__device__ float g_inv[4][NN];
__device__ float g_z[4][NN * 2];
__device__ float g_sum[4][NN * 2];

// ---------------- zero kernels ----------------
__global__ void k_zeroS() {
    size_t i = (size_t)blockIdx.x * blockDim.x + threadIdx.x;
    float4* p = (float4*)&g_s[0][0];
    if (i < (size_t)4 * NN * 128 / 4) p[i] = make_float4(0.f, 0.f, 0.f, 0.f);
}
__global__ void k_zeroMisc() {
    int i = blockIdx.x * blockDim.x + threadIdx.x;
    if (i < 4 * NN) ((int*)g_cnt)[i] = 0;
    if (i < 4 * NN * 2) ((float*)g_sum)[i] = 0.f;
}

// ---------------- build combined layer0 weights (bf16 hi/lo split, [n][k]) ----------------
__global__ void k_prep(const float* __restrict__ Wl_a, const float* __restrict__ Wl_b,
                       const float* __restrict__ Wr_a, const float* __restrict__ Wr_b,
                       const float* __restrict__ bl_a, const float* __restrict__ bl_b,
                       int type) {
    int idx = blockIdx.x * blockDim.x + threadIdx.x;
    if (idx < 256 * 384) {
        int n = idx / 384, k = idx - n * 384;
        float v;
        if (k < 128)       v = __ldg(Wl_a + n * 128 + k);
        else if (k < 256)  v = __ldg(Wl_b + n * 128 + (k - 128));
        else               v = __ldg(Wr_a + n * 128 + (k - 256)) + __ldg(Wr_b + n * 128 + (k - 256));
        __nv_bfloat16 hi = __float2bfloat16(v);
        __nv_bfloat16 lo = __float2bfloat16(v - __bfloat162float(hi));
        g_WBh[type][idx] = hi;
        g_WBl[type][idx] = lo;
    }
    if (idx < 256) g_bias[type][idx] = __ldg(bl_a + idx) + __ldg(bl_b + idx);
}

// ---------------- layer0 scatter: one warp per edge, red.v4, all 4 relations in one grid ----------------
__global__ __launch_bounds__(256) void k_scatter0(const float* __restrict__ x_tx,
                                                  const float* __restrict__ x_ad,
                                                  const int* __restrict__ e_tt,
                                                  const int* __restrict__ e_aa,
                                                  const int* __restrict__ e_at,
                                                  const int* __restrict__ e_ta) {
    int rel = blockIdx.y;
    const float* x = (rel == 0 || rel == 3) ? x_tx : x_ad;
    const int* e = (rel == 0) ? e_tt : (rel == 1) ? e_aa : (rel == 2) ? e_at : e_ta;
    int gt = blockIdx.x * blockDim.x + threadIdx.x;
    int w = gt >> 5, lane = gt & 31;
    if (w >= EE) return;
    int src = __ldg(e + w);
    int dst = __ldg(e + EE + w);
    float4 v = __ldg((const float4*)(x + (size_t)src * 128 + lane * 4));
    float* sp = g_s[rel] + (size_t)dst * 128 + lane * 4;
    asm volatile("red.global.add.v4.f32 [%0], {%1,%2,%3,%4};"
                 :: "l"(sp), "f"(v.x), "f"(v.y), "f"(v.z), "f"(v.w) : "memory");
    if (lane == 0) atomicAdd(&g_cnt[rel][dst], 1);
}

__global__ void k_inv() {
    int i = blockIdx.x * blockDim.x + threadIdx.x;
    if (i >= 4 * NN) return;
    int r = i / NN, n = i - r * NN;
    g_inv[r][n] = 1.0f / fmaxf((float)g_cnt[r][n], 1.0f);
}

// ---------------- tensor-core helpers ----------------
__device__ __forceinline__ void ldm4(uint32_t& r0, uint32_t& r1, uint32_t& r2, uint32_t& r3,
                                     uint32_t addr) {
    asm volatile("ldmatrix.sync.aligned.m8n8.x4.shared.b16 {%0,%1,%2,%3}, [%4];"
                 : "=r"(r0), "=r"(r1), "=r"(r2), "=r"(r3) : "r"(addr));
}
__device__ __forceinline__ void mma_bf16(float* c, uint32_t a0, uint32_t a1, uint32_t a2, uint32_t a3,
                                         uint32_t b0, uint32_t b1) {
    asm volatile("mma.sync.aligned.m16n8k16.row.col.f32.bf16.bf16.f32 "
                 "{%0,%1,%2,%3}, {%4,%5,%6,%7}, {%8,%9}, {%0,%1,%2,%3};"
                 : "+f"(c[0]), "+f"(c[1]), "+f"(c[2]), "+f"(c[3])
                 : "r"(a0), "r"(a1), "r"(a2), "r"(a3), "r"(b0), "r"(b1));
}
__device__ __forceinline__ uint32_t pkbf(__nv_bfloat16 a, __nv_bfloat16 b) {
    __nv_bfloat162 t = __halves2bfloat162(a, b);
    return *(uint32_t*)&t;
}

// ---------------- layer0 fused GEMM (tensor cores, bf16x3): [50000,384]x[384,256] + bias + relu ----
// A = [ s_A*invA | s_B*invB | x ] virtual concat. BM=128 BN=128 BK=32, 256 thr (8 warps 2x4).
#define KPAD 40
__global__ __launch_bounds__(256) void k_gemm0_tc(const float* __restrict__ x, int type) {
    __shared__ __align__(16) __nv_bfloat16 Ah[128][KPAD];
    __shared__ __align__(16) __nv_bfloat16 Al[128][KPAD];
    __shared__ __align__(16) __nv_bfloat16 Bh[128][KPAD];
    __shared__ __align__(16) __nv_bfloat16 Bl[128][KPAD];

    const float* sA = g_s[type];
    const float* sB = g_s[2 + type];
    float*       h  = g_h[type];

    const int tid = threadIdx.x;
    const int lane = tid & 31;
    const int wid = tid >> 5;
    const int rb = blockIdx.x * 128;
    const int nb = blockIdx.y * 128;
    const int wm = (wid >> 2) * 64;   // warp M base (0/64)
    const int wn = (wid & 3) * 32;    // warp N base (0/32/64/96)

    // per-thread staging row for loads
    const int row = tid >> 1;          // 0..127
    const int kq = (tid & 1) * 16;     // 0/16
    const bool okA = (rb + row) < NN;
    const size_t arow = (size_t)(okA ? (rb + row) : 0) * 128;
    const float s0 = okA ? g_inv[type][rb + row] : 0.f;
    const float s1 = okA ? g_inv[2 + type][rb + row] : 0.f;
    const __nv_bfloat16* wbh = g_WBh[type] + (size_t)(nb + row) * 384 + kq;
    const __nv_bfloat16* wbl = g_WBl[type] + (size_t)(nb + row) * 384 + kq;

    float acc[4][4][4];
#pragma unroll
    for (int i = 0; i < 4; i++)
#pragma unroll
        for (int j = 0; j < 4; j++)
#pragma unroll
            for (int q = 0; q < 4; q++) acc[i][j][q] = 0.f;

    // ldmatrix smem addresses (byte offsets within padded tiles)
    const int aRow = wm + (lane & 15);
    const int aCol = (lane >> 4) * 8;
    uint32_t aHiAddr = (uint32_t)__cvta_generic_to_shared(&Ah[aRow][aCol]);
    uint32_t aLoAddr = (uint32_t)__cvta_generic_to_shared(&Al[aRow][aCol]);
    const int bRow0 = wn + (lane & 7) + ((lane >> 4) * 8);
    const int bCol = ((lane >> 3) & 1) * 8;
    uint32_t bHiAddr0 = (uint32_t)__cvta_generic_to_shared(&Bh[bRow0][bCol]);
    uint32_t bHiAddr1 = (uint32_t)__cvta_generic_to_shared(&Bh[bRow0 + 16][bCol]);
    uint32_t bLoAddr0 = (uint32_t)__cvta_generic_to_shared(&Bl[bRow0][bCol]);
    uint32_t bLoAddr1 = (uint32_t)__cvta_generic_to_shared(&Bl[bRow0 + 16][bCol]);

    float av[16];
    uint4 bhv[2], blv[2];

    // prefetch chunk 0
    {
        const float* ap = sA + arow + kq;
#pragma unroll
        for (int u = 0; u < 4; ++u) {
            float4 v = okA ? __ldg((const float4*)(ap + 4 * u)) : make_float4(0.f, 0.f, 0.f, 0.f);
            av[4 * u] = v.x * s0; av[4 * u + 1] = v.y * s0; av[4 * u + 2] = v.z * s0; av[4 * u + 3] = v.w * s0;
        }
        bhv[0] = __ldg((const uint4*)wbh); bhv[1] = __ldg((const uint4*)(wbh + 8));
        blv[0] = __ldg((const uint4*)wbl); blv[1] = __ldg((const uint4*)(wbl + 8));
    }

#pragma unroll 1
    for (int c = 0; c < 12; ++c) {
        __syncthreads();
        // store staged chunk (split fp32 -> bf16 hi/lo)
        {
            __nv_bfloat16 th[16], tl[16];
#pragma unroll
            for (int u = 0; u < 16; ++u) {
                __nv_bfloat16 hi = __float2bfloat16(av[u]);
                th[u] = hi;
                tl[u] = __float2bfloat16(av[u] - __bfloat162float(hi));
            }
            uint4 uh0 = make_uint4(pkbf(th[0], th[1]), pkbf(th[2], th[3]), pkbf(th[4], th[5]), pkbf(th[6], th[7]));
            uint4 uh1 = make_uint4(pkbf(th[8], th[9]), pkbf(th[10], th[11]), pkbf(th[12], th[13]), pkbf(th[14], th[15]));
            uint4 ul0 = make_uint4(pkbf(tl[0], tl[1]), pkbf(tl[2], tl[3]), pkbf(tl[4], tl[5]), pkbf(tl[6], tl[7]));
            uint4 ul1 = make_uint4(pkbf(tl[8], tl[9]), pkbf(tl[10], tl[11]), pkbf(tl[12], tl[13]), pkbf(tl[14], tl[15]));
            *(uint4*)&Ah[row][kq] = uh0; *(uint4*)&Ah[row][kq + 8] = uh1;
            *(uint4*)&Al[row][kq] = ul0; *(uint4*)&Al[row][kq + 8] = ul1;
            *(uint4*)&Bh[row][kq] = bhv[0]; *(uint4*)&Bh[row][kq + 8] = bhv[1];
            *(uint4*)&Bl[row][kq] = blv[0]; *(uint4*)&Bl[row][kq + 8] = blv[1];
        }
        __syncthreads();

        // prefetch next chunk
        if (c < 11) {
            int nc = c + 1;
            int seg = nc >> 2, it = nc & 3;
            const float* sp = (seg == 0) ? sA : ((seg == 1) ? sB : x);
            float scale = (seg == 0) ? s0 : ((seg == 1) ? s1 : 1.f);
            const float* ap = sp + arow + it * 32 + kq;
#pragma unroll
            for (int u = 0; u < 4; ++u) {
                float4 v = okA ? __ldg((const float4*)(ap + 4 * u)) : make_float4(0.f, 0.f, 0.f, 0.f);
                av[4 * u] = v.x * scale; av[4 * u + 1] = v.y * scale; av[4 * u + 2] = v.z * scale; av[4 * u + 3] = v.w * scale;
            }
            const __nv_bfloat16* ph = wbh + nc * 32;
            const __nv_bfloat16* pl = wbl + nc * 32;
            bhv[0] = __ldg((const uint4*)ph); bhv[1] = __ldg((const uint4*)(ph + 8));
            blv[0] = __ldg((const uint4*)pl); blv[1] = __ldg((const uint4*)(pl + 8));
        }

        // compute: 2 k-steps of 16
#pragma unroll
        for (int ks = 0; ks < 2; ++ks) {
            uint32_t koff = ks * 32;  // 16 halves = 32 bytes
            uint32_t bh[8], bl[8];
            ldm4(bh[0], bh[1], bh[2], bh[3], bHiAddr0 + koff);
            ldm4(bh[4], bh[5], bh[6], bh[7], bHiAddr1 + koff);
            ldm4(bl[0], bl[1], bl[2], bl[3], bLoAddr0 + koff);
            ldm4(bl[4], bl[5], bl[6], bl[7], bLoAddr1 + koff);
#pragma unroll
            for (int mf = 0; mf < 4; ++mf) {
                uint32_t moff = mf * 16 * (KPAD * 2) + koff;
                uint32_t ah0, ah1, ah2, ah3, al0, al1, al2, al3;
                ldm4(ah0, ah1, ah2, ah3, aHiAddr + moff);
                ldm4(al0, al1, al2, al3, aLoAddr + moff);
#pragma unroll
                for (int nf = 0; nf < 4; ++nf) {
                    mma_bf16(acc[mf][nf], ah0, ah1, ah2, ah3, bh[2 * nf], bh[2 * nf + 1]);
                    mma_bf16(acc[mf][nf], al0, al1, al2, al3, bh[2 * nf], bh[2 * nf + 1]);
                    mma_bf16(acc[mf][nf], ah0, ah1, ah2, ah3, bl[2 * nf], bl[2 * nf + 1]);
                }
            }
        }
    }

    // epilogue: bias + relu, write h
    const int g = lane >> 2, t = lane & 3;
#pragma unroll
    for (int nf = 0; nf < 4; ++nf) {
        int col = nb + wn + nf * 8 + 2 * t;
        float bx = g_bias[type][col], by = g_bias[type][col + 1];
#pragma unroll
        for (int mf = 0; mf < 4; ++mf) {
            int r0 = rb + wm + mf * 16 + g;
            if (r0 < NN) {
                float2 o = make_float2(fmaxf(acc[mf][nf][0] + bx, 0.f), fmaxf(acc[mf][nf][1] + by, 0.f));
                *(float2*)&h[(size_t)r0 * 256 + col] = o;
            }
            if (r0 + 8 < NN) {
                float2 o = make_float2(fmaxf(acc[mf][nf][2] + bx, 0.f), fmaxf(acc[mf][nf][3] + by, 0.f));
                *(float2*)&h[(size_t)(r0 + 8) * 256 + col] = o;
            }
        }
    }
}

// ---------------- layer1 node transform: z (dim 2 per relation) + self term into out ----------------
__global__ __launch_bounds__(256) void k_l1(const float* __restrict__ WlA, const float* __restrict__ WlB,
                                            const float* __restrict__ WrA, const float* __restrict__ WrB,
                                            const float* __restrict__ blA, const float* __restrict__ blB,
                                            int type, float* __restrict__ out) {
    int gt = blockIdx.x * blockDim.x + threadIdx.x;
    int w = gt >> 5, lane = gt & 31;
    if (w >= NN) return;
    const float* hp = g_h[type] + (size_t)w * 256 + lane * 8;
    float4 h0 = __ldg((const float4*)hp);
    float4 h1 = __ldg((const float4*)(hp + 4));
    float hv[8] = {h0.x, h0.y, h0.z, h0.w, h1.x, h1.y, h1.z, h1.w};
    float a0 = 0, a1 = 0, a2 = 0, a3 = 0, a4 = 0, a5 = 0;
    int off = lane * 8;
#pragma unroll
    for (int u = 0; u < 8; ++u) {
        int k = off + u;
        float v = hv[u];
        a0 += v * __ldg(WlA + k);       a1 += v * __ldg(WlA + 256 + k);
        a2 += v * __ldg(WlB + k);       a3 += v * __ldg(WlB + 256 + k);
        a4 += v * (__ldg(WrA + k)       + __ldg(WrB + k));
        a5 += v * (__ldg(WrA + 256 + k) + __ldg(WrB + 256 + k));
    }
#pragma unroll
    for (int o = 16; o > 0; o >>= 1) {
        a0 += __shfl_xor_sync(0xffffffffu, a0, o);
        a1 += __shfl_xor_sync(0xffffffffu, a1, o);
        a2 += __shfl_xor_sync(0xffffffffu, a2, o);
        a3 += __shfl_xor_sync(0xffffffffu, a3, o);
        a4 += __shfl_xor_sync(0xffffffffu, a4, o);
        a5 += __shfl_xor_sync(0xffffffffu, a5, o);
    }
    if (lane == 0) {
        float* zA = g_z[type];
        float* zB = g_z[3 - type];
        zA[(size_t)w * 2]     = a0;
        zA[(size_t)w * 2 + 1] = a1;
        zB[(size_t)w * 2]     = a2;
        zB[(size_t)w * 2 + 1] = a3;
        out[(size_t)w * 2]     = a4 + __ldg(blA)     + __ldg(blB);
        out[(size_t)w * 2 + 1] = a5 + __ldg(blA + 1) + __ldg(blB + 1);
    }
}

// ---------------- layer1 scatter: thread per edge, dim 2 only ----------------
__global__ __launch_bounds__(256) void k_scatter1(const int* __restrict__ e_tt,
                                                  const int* __restrict__ e_aa,
                                                  const int* __restrict__ e_at,
                                                  const int* __restrict__ e_ta) {
    int rel = blockIdx.y;
    const int* e = (rel == 0) ? e_tt : (rel == 1) ? e_aa : (rel == 2) ? e_at : e_ta;
    int j = blockIdx.x * blockDim.x + threadIdx.x;
    if (j >= EE) return;
    int src = __ldg(e + j);
    int dst = __ldg(e + EE + j);
    const float* zp = g_z[rel] + (size_t)src * 2;
    float zx = __ldg(zp), zy = __ldg(zp + 1);
    float* sp = g_sum[rel] + (size_t)dst * 2;
    asm volatile("red.global.add.v2.f32 [%0], {%1,%2};"
                 :: "l"(sp), "f"(zx), "f"(zy) : "memory");
}

// ---------------- final combine: out += mean-agg of z ----------------
__global__ void k_combine(float* __restrict__ out) {
    int i = blockIdx.x * blockDim.x + threadIdx.x;
    if (i >= NN) return;
    float itt = g_inv[0][i], iaa = g_inv[1][i], iat = g_inv[2][i], ita = g_inv[3][i];
    size_t i2 = (size_t)i * 2;
    out[i2]     += g_sum[0][i2] * itt     + g_sum[2][i2] * iat;
    out[i2 + 1] += g_sum[0][i2 + 1] * itt + g_sum[2][i2 + 1] * iat;
    out[(size_t)NN * 2 + i2]     += g_sum[1][i2] * iaa     + g_sum[3][i2] * ita;
    out[(size_t)NN * 2 + i2 + 1] += g_sum[1][i2 + 1] * iaa + g_sum[3][i2 + 1] * ita;
}

extern "C" void kernel_launch(void* const* d_in, const int* in_sizes, int n_in,
                              void* d_out, int out_size) {
    const float* x_tx = (const float*)d_in[0];
    const float* x_ad = (const float*)d_in[1];
    const int* e_tt = (const int*)d_in[2];
    const int* e_aa = (const int*)d_in[3];
    const int* e_at = (const int*)d_in[4];
    const int* e_ta = (const int*)d_in[5];
    float* out = (float*)d_out;

    // zero scratch
    k_zeroS<<<25000, 256>>>();
    k_zeroMisc<<<1563, 256>>>();

    // combined layer0 weights (bf16 hi/lo, [n][k])
    k_prep<<<384, 256>>>((const float*)d_in[6],  (const float*)d_in[12],
                         (const float*)d_in[8],  (const float*)d_in[14],
                         (const float*)d_in[7],  (const float*)d_in[13], 0);
    k_prep<<<384, 256>>>((const float*)d_in[9],  (const float*)d_in[15],
                         (const float*)d_in[11], (const float*)d_in[17],
                         (const float*)d_in[10], (const float*)d_in[16], 1);

    // layer0 edge aggregation, all 4 relations in one grid
    k_scatter0<<<dim3(50000, 4), 256>>>(x_tx, x_ad, e_tt, e_aa, e_at, e_ta);
    k_inv<<<782, 256>>>();

    // layer0 fused GEMM + relu (tensor cores)
    k_gemm0_tc<<<dim3(391, 2), 256>>>(x_tx, 0);
    k_gemm0_tc<<<dim3(391, 2), 256>>>(x_ad, 1);

    // layer1 transform-first (dim 2), self term straight to out
    k_l1<<<6250, 256>>>((const float*)d_in[18], (const float*)d_in[27],
                        (const float*)d_in[20], (const float*)d_in[26],
                        (const float*)d_in[19], (const float*)d_in[25], 0, out);
    k_l1<<<6250, 256>>>((const float*)d_in[21], (const float*)d_in[24],
                        (const float*)d_in[23], (const float*)d_in[29],
                        (const float*)d_in[22], (const float*)d_in[28], 1, out + (size_t)NN * 2);

    // layer1 edge aggregation at dim 2
    k_scatter1<<<dim3(1563, 4), 256>>>(e_tt, e_aa, e_at, e_ta);

    k_combine<<<196, 256>>>(out);
}